// round 1
// baseline (speedup 1.0000x reference)
#include <cuda_runtime.h>
#include <math.h>

#define NTOK 8192
#define DIM 1024

// ---------------- scratch (device globals; no allocation) ----------------
__device__ float g_h[NTOK * DIM];        // LN output (reused for LN2)
__device__ float g_qkv[NTOK * 3 * DIM];  // QKV projection
__device__ float g_attno[NTOK * DIM];    // attention output
__device__ float g_x1[NTOK * DIM];       // residual after attention
__device__ float g_ff[NTOK * 4096];      // FC1+GELU output

// ---------------- LayerNorm: one block per row of 1024 ----------------
__global__ void __launch_bounds__(256) ln_kernel(
    const float* __restrict__ in, const float* __restrict__ w,
    const float* __restrict__ b, float* __restrict__ out) {
  const int row = blockIdx.x;
  const int tid = threadIdx.x;
  const float4 v = reinterpret_cast<const float4*>(in + (size_t)row * DIM)[tid];
  float s = v.x + v.y + v.z + v.w;
  float sq = v.x * v.x + v.y * v.y + v.z * v.z + v.w * v.w;
#pragma unroll
  for (int o = 16; o > 0; o >>= 1) {
    s += __shfl_xor_sync(0xffffffffu, s, o);
    sq += __shfl_xor_sync(0xffffffffu, sq, o);
  }
  __shared__ float rs[8], rq[8];
  const int warp = tid >> 5, lane = tid & 31;
  if (lane == 0) { rs[warp] = s; rq[warp] = sq; }
  __syncthreads();
  float st = 0.f, sqt = 0.f;
#pragma unroll
  for (int i = 0; i < 8; i++) { st += rs[i]; sqt += rq[i]; }
  const float mu = st * (1.0f / DIM);
  const float var = sqt * (1.0f / DIM) - mu * mu;
  const float rstd = rsqrtf(var + 1e-5f);
  const float4 wv = reinterpret_cast<const float4*>(w)[tid];
  const float4 bv = reinterpret_cast<const float4*>(b)[tid];
  float4 o;
  o.x = (v.x - mu) * rstd * wv.x + bv.x;
  o.y = (v.y - mu) * rstd * wv.y + bv.y;
  o.z = (v.z - mu) * rstd * wv.z + bv.z;
  o.w = (v.w - mu) * rstd * wv.w + bv.w;
  reinterpret_cast<float4*>(out + (size_t)row * DIM)[tid] = o;
}

// ---------------- SGEMM NT: C[M,N] = A[M,K] @ W[N,K]^T + bias (+epilogue) ----
// EPI: 0 = bias, 1 = bias + residual, 2 = bias + exact GELU
// BM=BN=128, BK=16, 256 threads, 8x8 per-thread microtile.
template <int EPI>
__global__ void __launch_bounds__(256) sgemm_nt(
    const float* __restrict__ A, const float* __restrict__ W,
    const float* __restrict__ bias, const float* __restrict__ res,
    float* __restrict__ C, int M, int N, int K) {
  __shared__ float As[16][128];
  __shared__ float Bs[16][128];
  const int bm = blockIdx.y * 128;
  const int bn = blockIdx.x * 128;
  const int tid = threadIdx.x;
  const int tx = tid & 15, ty = tid >> 4;
  float acc[8][8];
#pragma unroll
  for (int i = 0; i < 8; i++)
#pragma unroll
    for (int j = 0; j < 8; j++) acc[i][j] = 0.f;

  const int lrow = tid >> 2;          // 0..63
  const int lk = (tid & 3) * 4;       // 0,4,8,12

  for (int k0 = 0; k0 < K; k0 += 16) {
#pragma unroll
    for (int i = 0; i < 2; i++) {
      const int row = lrow + i * 64;
      const float4 va = *reinterpret_cast<const float4*>(
          A + (size_t)(bm + row) * K + k0 + lk);
      As[lk + 0][row] = va.x; As[lk + 1][row] = va.y;
      As[lk + 2][row] = va.z; As[lk + 3][row] = va.w;
      const float4 vb = *reinterpret_cast<const float4*>(
          W + (size_t)(bn + row) * K + k0 + lk);
      Bs[lk + 0][row] = vb.x; Bs[lk + 1][row] = vb.y;
      Bs[lk + 2][row] = vb.z; Bs[lk + 3][row] = vb.w;
    }
    __syncthreads();
#pragma unroll
    for (int kk = 0; kk < 16; kk++) {
      float a[8], b[8];
      *reinterpret_cast<float4*>(&a[0]) = *reinterpret_cast<float4*>(&As[kk][ty * 8]);
      *reinterpret_cast<float4*>(&a[4]) = *reinterpret_cast<float4*>(&As[kk][ty * 8 + 4]);
      *reinterpret_cast<float4*>(&b[0]) = *reinterpret_cast<float4*>(&Bs[kk][tx * 8]);
      *reinterpret_cast<float4*>(&b[4]) = *reinterpret_cast<float4*>(&Bs[kk][tx * 8 + 4]);
#pragma unroll
      for (int i = 0; i < 8; i++)
#pragma unroll
        for (int j = 0; j < 8; j++) acc[i][j] = fmaf(a[i], b[j], acc[i][j]);
    }
    __syncthreads();
  }

#pragma unroll
  for (int i = 0; i < 8; i++) {
    const int row = bm + ty * 8 + i;
#pragma unroll
    for (int j = 0; j < 8; j += 4) {
      const int col = bn + tx * 8 + j;
      const float4 bb = *reinterpret_cast<const float4*>(bias + col);
      float4 o;
      o.x = acc[i][j + 0] + bb.x;
      o.y = acc[i][j + 1] + bb.y;
      o.z = acc[i][j + 2] + bb.z;
      o.w = acc[i][j + 3] + bb.w;
      if (EPI == 1) {
        const float4 rr = *reinterpret_cast<const float4*>(
            res + (size_t)row * N + col);
        o.x += rr.x; o.y += rr.y; o.z += rr.z; o.w += rr.w;
      } else if (EPI == 2) {
        o.x = 0.5f * o.x * (1.0f + erff(o.x * 0.70710678118654752f));
        o.y = 0.5f * o.y * (1.0f + erff(o.y * 0.70710678118654752f));
        o.z = 0.5f * o.z * (1.0f + erff(o.z * 0.70710678118654752f));
        o.w = 0.5f * o.w * (1.0f + erff(o.w * 0.70710678118654752f));
      }
      *reinterpret_cast<float4*>(C + (size_t)row * N + col) = o;
    }
  }
}

// ---------------- Flash attention: 64 q-rows per block, online softmax ------
// qkv layout: [b*1024+s, 3*1024]; q at +0, k at +1024, v at +2048, head h at h*64.
// Block: 256 threads = 16x16 (ty,tx); thread owns S[4r x 4c] and O[4r x 4d].
#define AS 68  // padded smem stride (floats)
__global__ void __launch_bounds__(256) attn_kernel(
    const float* __restrict__ qkv, float* __restrict__ out) {
  extern __shared__ float sm[];
  float* Qs = sm;                 // [64][AS]  row-major (r, d)
  float* KsT = sm + 64 * AS;      // [64][AS]  (d, c)  transposed
  float* Vs = sm + 2 * 64 * AS;   // [64][AS]  (c, d)
  float* Ps = sm + 3 * 64 * AS;   // [64][AS]  (r, c)

  const int tid = threadIdx.x;
  const int tx = tid & 15, ty = tid >> 4;
  const int bh = blockIdx.y;
  const int b = bh >> 4, h = bh & 15;
  const int q0 = blockIdx.x * 64;
  const size_t base = (size_t)b * 1024 * 3072 + (size_t)h * 64;

  // load Q tile [64 x 64]
#pragma unroll
  for (int i = 0; i < 4; i++) {
    const int ff = tid + i * 256;
    const int row = ff >> 4;
    const int d4 = (ff & 15) * 4;
    const float4 v = *reinterpret_cast<const float4*>(
        qkv + base + (size_t)(q0 + row) * 3072 + d4);
    Qs[row * AS + d4 + 0] = v.x; Qs[row * AS + d4 + 1] = v.y;
    Qs[row * AS + d4 + 2] = v.z; Qs[row * AS + d4 + 3] = v.w;
  }

  float m_prev[4], l[4], o_acc[4][4];
#pragma unroll
  for (int i = 0; i < 4; i++) {
    m_prev[i] = -INFINITY; l[i] = 0.f;
#pragma unroll
    for (int j = 0; j < 4; j++) o_acc[i][j] = 0.f;
  }

  for (int t = 0; t < 16; t++) {
    __syncthreads();  // prev iteration fully consumed KsT/Vs/Ps; Qs visible at t=0
    // load K (transposed) and V tiles, kv rows t*64..t*64+63
#pragma unroll
    for (int i = 0; i < 4; i++) {
      const int ff = tid + i * 256;
      const int row = ff >> 4;
      const int d4 = (ff & 15) * 4;
      const size_t roff = base + (size_t)(t * 64 + row) * 3072 + d4;
      const float4 kv = *reinterpret_cast<const float4*>(qkv + roff + 1024);
      KsT[(d4 + 0) * AS + row] = kv.x; KsT[(d4 + 1) * AS + row] = kv.y;
      KsT[(d4 + 2) * AS + row] = kv.z; KsT[(d4 + 3) * AS + row] = kv.w;
      const float4 vv = *reinterpret_cast<const float4*>(qkv + roff + 2048);
      Vs[row * AS + d4 + 0] = vv.x; Vs[row * AS + d4 + 1] = vv.y;
      Vs[row * AS + d4 + 2] = vv.z; Vs[row * AS + d4 + 3] = vv.w;
    }
    __syncthreads();

    // S = Q K^T (scaled)
    float s[4][4];
#pragma unroll
    for (int i = 0; i < 4; i++)
#pragma unroll
      for (int j = 0; j < 4; j++) s[i][j] = 0.f;
#pragma unroll 4
    for (int k = 0; k < 64; k++) {
      const float4 kb = *reinterpret_cast<float4*>(&KsT[k * AS + tx * 4]);
#pragma unroll
      for (int i = 0; i < 4; i++) {
        const float qa = Qs[(ty * 4 + i) * AS + k];
        s[i][0] = fmaf(qa, kb.x, s[i][0]);
        s[i][1] = fmaf(qa, kb.y, s[i][1]);
        s[i][2] = fmaf(qa, kb.z, s[i][2]);
        s[i][3] = fmaf(qa, kb.w, s[i][3]);
      }
    }

    // online softmax per row (reduce across 16 lanes holding the 64 cols)
#pragma unroll
    for (int i = 0; i < 4; i++) {
      float mx = fmaxf(fmaxf(s[i][0], s[i][1]), fmaxf(s[i][2], s[i][3])) * 0.125f;
#pragma unroll
      for (int o = 1; o < 16; o <<= 1)
        mx = fmaxf(mx, __shfl_xor_sync(0xffffffffu, mx, o, 16));
      const float mnew = fmaxf(m_prev[i], mx);
      const float p0 = expf(s[i][0] * 0.125f - mnew);
      const float p1 = expf(s[i][1] * 0.125f - mnew);
      const float p2 = expf(s[i][2] * 0.125f - mnew);
      const float p3 = expf(s[i][3] * 0.125f - mnew);
      float rsum = p0 + p1 + p2 + p3;
#pragma unroll
      for (int o = 1; o < 16; o <<= 1)
        rsum += __shfl_xor_sync(0xffffffffu, rsum, o, 16);
      const float c = expf(m_prev[i] - mnew);
      l[i] = l[i] * c + rsum;
      m_prev[i] = mnew;
      o_acc[i][0] *= c; o_acc[i][1] *= c; o_acc[i][2] *= c; o_acc[i][3] *= c;
      *reinterpret_cast<float4*>(&Ps[(ty * 4 + i) * AS + tx * 4]) =
          make_float4(p0, p1, p2, p3);
    }
    __syncthreads();

    // O += P V
#pragma unroll 4
    for (int c = 0; c < 64; c++) {
      const float4 vb = *reinterpret_cast<float4*>(&Vs[c * AS + tx * 4]);
#pragma unroll
      for (int i = 0; i < 4; i++) {
        const float p = Ps[(ty * 4 + i) * AS + c];
        o_acc[i][0] = fmaf(p, vb.x, o_acc[i][0]);
        o_acc[i][1] = fmaf(p, vb.y, o_acc[i][1]);
        o_acc[i][2] = fmaf(p, vb.z, o_acc[i][2]);
        o_acc[i][3] = fmaf(p, vb.w, o_acc[i][3]);
      }
    }
  }

#pragma unroll
  for (int i = 0; i < 4; i++) {
    const float inv = 1.0f / l[i];
    const int row = q0 + ty * 4 + i;
    *reinterpret_cast<float4*>(out + (size_t)(b * 1024 + row) * 1024 + h * 64 + tx * 4) =
        make_float4(o_acc[i][0] * inv, o_acc[i][1] * inv,
                    o_acc[i][2] * inv, o_acc[i][3] * inv);
  }
}

// ---------------- launch ----------------
extern "C" void kernel_launch(void* const* d_in, const int* in_sizes, int n_in,
                              void* d_out, int out_size) {
  const float* x = (const float*)d_in[0];
  const float* ln1w = (const float*)d_in[1];
  const float* ln1b = (const float*)d_in[2];
  const float* qkvw = (const float*)d_in[3];
  const float* qkvb = (const float*)d_in[4];
  const float* outw = (const float*)d_in[5];
  const float* outb = (const float*)d_in[6];
  const float* ln2w = (const float*)d_in[7];
  const float* ln2b = (const float*)d_in[8];
  const float* fc1w = (const float*)d_in[9];
  const float* fc1b = (const float*)d_in[10];
  const float* fc2w = (const float*)d_in[11];
  const float* fc2b = (const float*)d_in[12];
  float* out = (float*)d_out;

  float *h, *qkv, *attno, *x1, *ff;
  cudaGetSymbolAddress((void**)&h, g_h);
  cudaGetSymbolAddress((void**)&qkv, g_qkv);
  cudaGetSymbolAddress((void**)&attno, g_attno);
  cudaGetSymbolAddress((void**)&x1, g_x1);
  cudaGetSymbolAddress((void**)&ff, g_ff);

  cudaFuncSetAttribute(attn_kernel,
                       cudaFuncAttributeMaxDynamicSharedMemorySize, 4 * 64 * AS * 4);

  // LN1
  ln_kernel<<<NTOK, 256>>>(x, ln1w, ln1b, h);
  // QKV: [8192,1024] @ [3072,1024]^T
  sgemm_nt<0><<<dim3(3072 / 128, NTOK / 128), 256>>>(h, qkvw, qkvb, nullptr, qkv,
                                                     NTOK, 3072, 1024);
  // attention
  attn_kernel<<<dim3(16, 128), 256, 4 * 64 * AS * 4>>>(qkv, attno);
  // out projection + residual
  sgemm_nt<1><<<dim3(1024 / 128, NTOK / 128), 256>>>(attno, outw, outb, x, x1,
                                                     NTOK, 1024, 1024);
  // LN2
  ln_kernel<<<NTOK, 256>>>(x1, ln2w, ln2b, h);
  // FC1 + GELU
  sgemm_nt<2><<<dim3(4096 / 128, NTOK / 128), 256>>>(h, fc1w, fc1b, nullptr, ff,
                                                     NTOK, 4096, 1024);
  // FC2 + residual -> output
  sgemm_nt<1><<<dim3(1024 / 128, NTOK / 128), 256>>>(ff, fc2w, fc2b, x1, out,
                                                     NTOK, 1024, 4096);
}

// round 2
// speedup vs baseline: 2.2237x; 2.2237x over previous
#include <cuda_runtime.h>
#include <math.h>
#include <stdint.h>

#define NTOK 8192
#define DIM 1024

// ---------------- scratch (device globals; no allocation) ----------------
__device__ float g_h[NTOK * DIM];        // LN output (reused for LN2)
__device__ float g_qkv[NTOK * 3 * DIM];  // QKV projection
__device__ float g_attno[NTOK * DIM];    // attention output
__device__ float g_x1[NTOK * DIM];       // residual after attention
__device__ float g_ff[NTOK * 4096];      // FC1+GELU output

// ---------------- LayerNorm: one block per row of 1024 ----------------
__global__ void __launch_bounds__(256) ln_kernel(
    const float* __restrict__ in, const float* __restrict__ w,
    const float* __restrict__ b, float* __restrict__ out) {
  const int row = blockIdx.x;
  const int tid = threadIdx.x;
  const float4 v = reinterpret_cast<const float4*>(in + (size_t)row * DIM)[tid];
  float s = v.x + v.y + v.z + v.w;
  float sq = v.x * v.x + v.y * v.y + v.z * v.z + v.w * v.w;
#pragma unroll
  for (int o = 16; o > 0; o >>= 1) {
    s += __shfl_xor_sync(0xffffffffu, s, o);
    sq += __shfl_xor_sync(0xffffffffu, sq, o);
  }
  __shared__ float rs[8], rq[8];
  const int warp = tid >> 5, lane = tid & 31;
  if (lane == 0) { rs[warp] = s; rq[warp] = sq; }
  __syncthreads();
  float st = 0.f, sqt = 0.f;
#pragma unroll
  for (int i = 0; i < 8; i++) { st += rs[i]; sqt += rq[i]; }
  const float mu = st * (1.0f / DIM);
  const float var = sqt * (1.0f / DIM) - mu * mu;
  const float rstd = rsqrtf(var + 1e-5f);
  const float4 wv = reinterpret_cast<const float4*>(w)[tid];
  const float4 bv = reinterpret_cast<const float4*>(b)[tid];
  float4 o;
  o.x = (v.x - mu) * rstd * wv.x + bv.x;
  o.y = (v.y - mu) * rstd * wv.y + bv.y;
  o.z = (v.z - mu) * rstd * wv.z + bv.z;
  o.w = (v.w - mu) * rstd * wv.w + bv.w;
  reinterpret_cast<float4*>(out + (size_t)row * DIM)[tid] = o;
}

// ---------------- tf32 tensor-core GEMM NT ----------------
// C[M,N] = A[M,K] @ W[N,K]^T + bias (+epilogue)
// EPI: 0 = bias, 1 = bias + residual, 2 = bias + exact GELU
// CTA tile 128x128x32, 256 threads (8 warps), warp tile 32x64.
// mma.sync.aligned.m16n8k8.row.col.f32.tf32.tf32.f32
#define ASTR 36  // padded smem row stride (floats): conflict-free frag loads

__device__ __forceinline__ float to_tf32(float x) {
  uint32_t u;
  asm("cvt.rna.tf32.f32 %0, %1;" : "=r"(u) : "f"(x));
  return __uint_as_float(u);
}

template <int EPI>
__global__ void __launch_bounds__(256) mma_nt(
    const float* __restrict__ A, const float* __restrict__ W,
    const float* __restrict__ bias, const float* __restrict__ res,
    float* __restrict__ C, int M, int N, int K) {
  extern __shared__ float sm[];
  // As[2][128][ASTR] at sm, Bs[2][128][ASTR] at sm + 2*128*ASTR
  float* const Asm = sm;
  float* const Bsm = sm + 2 * 128 * ASTR;

  const int bm = blockIdx.y * 128;
  const int bn = blockIdx.x * 128;
  const int tid = threadIdx.x;
  const int lane = tid & 31;
  const int warp = tid >> 5;
  const int wm = (warp >> 1) * 32;  // warp M offset in tile
  const int wn = (warp & 1) * 64;   // warp N offset in tile

  const int lg = lane >> 2;   // 0..7  (group)
  const int lt = lane & 3;    // 0..3  (thread-in-group)

  float acc[2][8][4];
#pragma unroll
  for (int mt = 0; mt < 2; mt++)
#pragma unroll
    for (int nt = 0; nt < 8; nt++)
#pragma unroll
      for (int i = 0; i < 4; i++) acc[mt][nt][i] = 0.f;

  // gmem->reg staging mapping: 4 rows strided 32, 4 cols
  const int lr = tid >> 3;        // 0..31
  const int lc = (tid & 7) * 4;   // 0,4,...,28
  float4 ra[4], rb[4];

  const int NIT = K >> 5;

  // prologue: tile 0
#pragma unroll
  for (int i = 0; i < 4; i++) {
    ra[i] = *reinterpret_cast<const float4*>(A + (size_t)(bm + lr + i * 32) * K + lc);
    rb[i] = *reinterpret_cast<const float4*>(W + (size_t)(bn + lr + i * 32) * K + lc);
  }
#pragma unroll
  for (int i = 0; i < 4; i++) {
    float* pa = Asm + (lr + i * 32) * ASTR + lc;
    pa[0] = to_tf32(ra[i].x); pa[1] = to_tf32(ra[i].y);
    pa[2] = to_tf32(ra[i].z); pa[3] = to_tf32(ra[i].w);
    float* pb = Bsm + (lr + i * 32) * ASTR + lc;
    pb[0] = to_tf32(rb[i].x); pb[1] = to_tf32(rb[i].y);
    pb[2] = to_tf32(rb[i].z); pb[3] = to_tf32(rb[i].w);
  }
  __syncthreads();

  for (int it = 0; it < NIT; it++) {
    const int buf = it & 1;
    if (it + 1 < NIT) {
      const int k0 = (it + 1) << 5;
#pragma unroll
      for (int i = 0; i < 4; i++) {
        ra[i] = *reinterpret_cast<const float4*>(A + (size_t)(bm + lr + i * 32) * K + k0 + lc);
        rb[i] = *reinterpret_cast<const float4*>(W + (size_t)(bn + lr + i * 32) * K + k0 + lc);
      }
    }

    const float* Ab = Asm + buf * 128 * ASTR;
    const float* Bb = Bsm + buf * 128 * ASTR;
#pragma unroll
    for (int kk = 0; kk < 4; kk++) {
      const int k = kk * 8;
      uint32_t af[2][4];
#pragma unroll
      for (int mt = 0; mt < 2; mt++) {
        const int rbase = wm + mt * 16;
        af[mt][0] = __float_as_uint(Ab[(rbase + lg) * ASTR + k + lt]);
        af[mt][1] = __float_as_uint(Ab[(rbase + 8 + lg) * ASTR + k + lt]);
        af[mt][2] = __float_as_uint(Ab[(rbase + lg) * ASTR + k + 4 + lt]);
        af[mt][3] = __float_as_uint(Ab[(rbase + 8 + lg) * ASTR + k + 4 + lt]);
      }
#pragma unroll
      for (int nt = 0; nt < 8; nt++) {
        const int nbase = wn + nt * 8;
        uint32_t b0 = __float_as_uint(Bb[(nbase + lg) * ASTR + k + lt]);
        uint32_t b1 = __float_as_uint(Bb[(nbase + lg) * ASTR + k + 4 + lt]);
#pragma unroll
        for (int mt = 0; mt < 2; mt++) {
          asm volatile(
              "mma.sync.aligned.m16n8k8.row.col.f32.tf32.tf32.f32 "
              "{%0,%1,%2,%3}, {%4,%5,%6,%7}, {%8,%9}, {%0,%1,%2,%3};"
              : "+f"(acc[mt][nt][0]), "+f"(acc[mt][nt][1]),
                "+f"(acc[mt][nt][2]), "+f"(acc[mt][nt][3])
              : "r"(af[mt][0]), "r"(af[mt][1]), "r"(af[mt][2]), "r"(af[mt][3]),
                "r"(b0), "r"(b1));
        }
      }
    }

    if (it + 1 < NIT) {
      const int nbuf = (it + 1) & 1;
      float* Aw = Asm + nbuf * 128 * ASTR;
      float* Bw = Bsm + nbuf * 128 * ASTR;
#pragma unroll
      for (int i = 0; i < 4; i++) {
        float* pa = Aw + (lr + i * 32) * ASTR + lc;
        pa[0] = to_tf32(ra[i].x); pa[1] = to_tf32(ra[i].y);
        pa[2] = to_tf32(ra[i].z); pa[3] = to_tf32(ra[i].w);
        float* pb = Bw + (lr + i * 32) * ASTR + lc;
        pb[0] = to_tf32(rb[i].x); pb[1] = to_tf32(rb[i].y);
        pb[2] = to_tf32(rb[i].z); pb[3] = to_tf32(rb[i].w);
      }
    }
    __syncthreads();
  }

  // epilogue
#pragma unroll
  for (int mt = 0; mt < 2; mt++) {
#pragma unroll
    for (int nt = 0; nt < 8; nt++) {
      const int c0 = bn + wn + nt * 8 + 2 * lt;
      const float2 bb = *reinterpret_cast<const float2*>(bias + c0);
#pragma unroll
      for (int rh = 0; rh < 2; rh++) {
        const int row = bm + wm + mt * 16 + lg + rh * 8;
        float2 o;
        o.x = acc[mt][nt][rh * 2 + 0] + bb.x;
        o.y = acc[mt][nt][rh * 2 + 1] + bb.y;
        if (EPI == 1) {
          const float2 rr = *reinterpret_cast<const float2*>(res + (size_t)row * N + c0);
          o.x += rr.x; o.y += rr.y;
        } else if (EPI == 2) {
          o.x = 0.5f * o.x * (1.0f + erff(o.x * 0.70710678118654752f));
          o.y = 0.5f * o.y * (1.0f + erff(o.y * 0.70710678118654752f));
        }
        *reinterpret_cast<float2*>(C + (size_t)row * N + c0) = o;
      }
    }
  }
}

#define MMA_SMEM (4 * 128 * ASTR * 4)

// ---------------- Flash attention: 64 q-rows per block, online softmax ------
#define AS 68  // padded smem stride (floats)
__global__ void __launch_bounds__(256) attn_kernel(
    const float* __restrict__ qkv, float* __restrict__ out) {
  extern __shared__ float smattn[];
  float* Qs = smattn;
  float* KsT = smattn + 64 * AS;
  float* Vs = smattn + 2 * 64 * AS;
  float* Ps = smattn + 3 * 64 * AS;

  const int tid = threadIdx.x;
  const int tx = tid & 15, ty = tid >> 4;
  const int bh = blockIdx.y;
  const int b = bh >> 4, h = bh & 15;
  const int q0 = blockIdx.x * 64;
  const size_t base = (size_t)b * 1024 * 3072 + (size_t)h * 64;

#pragma unroll
  for (int i = 0; i < 4; i++) {
    const int ff = tid + i * 256;
    const int row = ff >> 4;
    const int d4 = (ff & 15) * 4;
    const float4 v = *reinterpret_cast<const float4*>(
        qkv + base + (size_t)(q0 + row) * 3072 + d4);
    Qs[row * AS + d4 + 0] = v.x; Qs[row * AS + d4 + 1] = v.y;
    Qs[row * AS + d4 + 2] = v.z; Qs[row * AS + d4 + 3] = v.w;
  }

  float m_prev[4], l[4], o_acc[4][4];
#pragma unroll
  for (int i = 0; i < 4; i++) {
    m_prev[i] = -INFINITY; l[i] = 0.f;
#pragma unroll
    for (int j = 0; j < 4; j++) o_acc[i][j] = 0.f;
  }

  for (int t = 0; t < 16; t++) {
    __syncthreads();
#pragma unroll
    for (int i = 0; i < 4; i++) {
      const int ff = tid + i * 256;
      const int row = ff >> 4;
      const int d4 = (ff & 15) * 4;
      const size_t roff = base + (size_t)(t * 64 + row) * 3072 + d4;
      const float4 kv = *reinterpret_cast<const float4*>(qkv + roff + 1024);
      KsT[(d4 + 0) * AS + row] = kv.x; KsT[(d4 + 1) * AS + row] = kv.y;
      KsT[(d4 + 2) * AS + row] = kv.z; KsT[(d4 + 3) * AS + row] = kv.w;
      const float4 vv = *reinterpret_cast<const float4*>(qkv + roff + 2048);
      Vs[row * AS + d4 + 0] = vv.x; Vs[row * AS + d4 + 1] = vv.y;
      Vs[row * AS + d4 + 2] = vv.z; Vs[row * AS + d4 + 3] = vv.w;
    }
    __syncthreads();

    float s[4][4];
#pragma unroll
    for (int i = 0; i < 4; i++)
#pragma unroll
      for (int j = 0; j < 4; j++) s[i][j] = 0.f;
#pragma unroll 4
    for (int k = 0; k < 64; k++) {
      const float4 kb = *reinterpret_cast<float4*>(&KsT[k * AS + tx * 4]);
#pragma unroll
      for (int i = 0; i < 4; i++) {
        const float qa = Qs[(ty * 4 + i) * AS + k];
        s[i][0] = fmaf(qa, kb.x, s[i][0]);
        s[i][1] = fmaf(qa, kb.y, s[i][1]);
        s[i][2] = fmaf(qa, kb.z, s[i][2]);
        s[i][3] = fmaf(qa, kb.w, s[i][3]);
      }
    }

#pragma unroll
    for (int i = 0; i < 4; i++) {
      float mx = fmaxf(fmaxf(s[i][0], s[i][1]), fmaxf(s[i][2], s[i][3])) * 0.125f;
#pragma unroll
      for (int o = 1; o < 16; o <<= 1)
        mx = fmaxf(mx, __shfl_xor_sync(0xffffffffu, mx, o, 16));
      const float mnew = fmaxf(m_prev[i], mx);
      const float p0 = expf(s[i][0] * 0.125f - mnew);
      const float p1 = expf(s[i][1] * 0.125f - mnew);
      const float p2 = expf(s[i][2] * 0.125f - mnew);
      const float p3 = expf(s[i][3] * 0.125f - mnew);
      float rsum = p0 + p1 + p2 + p3;
#pragma unroll
      for (int o = 1; o < 16; o <<= 1)
        rsum += __shfl_xor_sync(0xffffffffu, rsum, o, 16);
      const float c = expf(m_prev[i] - mnew);
      l[i] = l[i] * c + rsum;
      m_prev[i] = mnew;
      o_acc[i][0] *= c; o_acc[i][1] *= c; o_acc[i][2] *= c; o_acc[i][3] *= c;
      *reinterpret_cast<float4*>(&Ps[(ty * 4 + i) * AS + tx * 4]) =
          make_float4(p0, p1, p2, p3);
    }
    __syncthreads();

#pragma unroll 4
    for (int c = 0; c < 64; c++) {
      const float4 vb = *reinterpret_cast<float4*>(&Vs[c * AS + tx * 4]);
#pragma unroll
      for (int i = 0; i < 4; i++) {
        const float p = Ps[(ty * 4 + i) * AS + c];
        o_acc[i][0] = fmaf(p, vb.x, o_acc[i][0]);
        o_acc[i][1] = fmaf(p, vb.y, o_acc[i][1]);
        o_acc[i][2] = fmaf(p, vb.z, o_acc[i][2]);
        o_acc[i][3] = fmaf(p, vb.w, o_acc[i][3]);
      }
    }
  }

#pragma unroll
  for (int i = 0; i < 4; i++) {
    const float inv = 1.0f / l[i];
    const int row = q0 + ty * 4 + i;
    *reinterpret_cast<float4*>(out + (size_t)(b * 1024 + row) * 1024 + h * 64 + tx * 4) =
        make_float4(o_acc[i][0] * inv, o_acc[i][1] * inv,
                    o_acc[i][2] * inv, o_acc[i][3] * inv);
  }
}

// ---------------- launch ----------------
extern "C" void kernel_launch(void* const* d_in, const int* in_sizes, int n_in,
                              void* d_out, int out_size) {
  const float* x = (const float*)d_in[0];
  const float* ln1w = (const float*)d_in[1];
  const float* ln1b = (const float*)d_in[2];
  const float* qkvw = (const float*)d_in[3];
  const float* qkvb = (const float*)d_in[4];
  const float* outw = (const float*)d_in[5];
  const float* outb = (const float*)d_in[6];
  const float* ln2w = (const float*)d_in[7];
  const float* ln2b = (const float*)d_in[8];
  const float* fc1w = (const float*)d_in[9];
  const float* fc1b = (const float*)d_in[10];
  const float* fc2w = (const float*)d_in[11];
  const float* fc2b = (const float*)d_in[12];
  float* out = (float*)d_out;

  float *h, *qkv, *attno, *x1, *ff;
  cudaGetSymbolAddress((void**)&h, g_h);
  cudaGetSymbolAddress((void**)&qkv, g_qkv);
  cudaGetSymbolAddress((void**)&attno, g_attno);
  cudaGetSymbolAddress((void**)&x1, g_x1);
  cudaGetSymbolAddress((void**)&ff, g_ff);

  cudaFuncSetAttribute(attn_kernel,
                       cudaFuncAttributeMaxDynamicSharedMemorySize, 4 * 64 * AS * 4);
  cudaFuncSetAttribute(mma_nt<0>,
                       cudaFuncAttributeMaxDynamicSharedMemorySize, MMA_SMEM);
  cudaFuncSetAttribute(mma_nt<1>,
                       cudaFuncAttributeMaxDynamicSharedMemorySize, MMA_SMEM);
  cudaFuncSetAttribute(mma_nt<2>,
                       cudaFuncAttributeMaxDynamicSharedMemorySize, MMA_SMEM);

  // LN1
  ln_kernel<<<NTOK, 256>>>(x, ln1w, ln1b, h);
  // QKV: [8192,1024] @ [3072,1024]^T
  mma_nt<0><<<dim3(3072 / 128, NTOK / 128), 256, MMA_SMEM>>>(
      h, qkvw, qkvb, nullptr, qkv, NTOK, 3072, 1024);
  // attention
  attn_kernel<<<dim3(16, 128), 256, 4 * 64 * AS * 4>>>(qkv, attno);
  // out projection + residual
  mma_nt<1><<<dim3(1024 / 128, NTOK / 128), 256, MMA_SMEM>>>(
      attno, outw, outb, x, x1, NTOK, 1024, 1024);
  // LN2
  ln_kernel<<<NTOK, 256>>>(x1, ln2w, ln2b, h);
  // FC1 + GELU
  mma_nt<2><<<dim3(4096 / 128, NTOK / 128), 256, MMA_SMEM>>>(
      h, fc1w, fc1b, nullptr, ff, NTOK, 4096, 1024);
  // FC2 + residual -> output
  mma_nt<1><<<dim3(1024 / 128, NTOK / 128), 256, MMA_SMEM>>>(
      ff, fc2w, fc2b, x1, out, NTOK, 1024, 4096);
}

// round 3
// speedup vs baseline: 2.9192x; 1.3127x over previous
#include <cuda_runtime.h>
#include <math.h>
#include <stdint.h>

#define NTOK 8192
#define DIM 1024

// ---------------- scratch (device globals; no allocation) ----------------
__device__ float g_h[NTOK * DIM];
__device__ float g_qkv[NTOK * 3 * DIM];
__device__ float g_attno[NTOK * DIM];
__device__ float g_x1[NTOK * DIM];
__device__ float g_ff[NTOK * 4096];

__device__ __forceinline__ float to_tf32(float x) {
  uint32_t u;
  asm("cvt.rna.tf32.f32 %0, %1;" : "=r"(u) : "f"(x));
  return __uint_as_float(u);
}

// ---------------- LayerNorm ----------------
__global__ void __launch_bounds__(256) ln_kernel(
    const float* __restrict__ in, const float* __restrict__ w,
    const float* __restrict__ b, float* __restrict__ out) {
  const int row = blockIdx.x;
  const int tid = threadIdx.x;
  const float4 v = reinterpret_cast<const float4*>(in + (size_t)row * DIM)[tid];
  float s = v.x + v.y + v.z + v.w;
  float sq = v.x * v.x + v.y * v.y + v.z * v.z + v.w * v.w;
#pragma unroll
  for (int o = 16; o > 0; o >>= 1) {
    s += __shfl_xor_sync(0xffffffffu, s, o);
    sq += __shfl_xor_sync(0xffffffffu, sq, o);
  }
  __shared__ float rs[8], rq[8];
  const int warp = tid >> 5, lane = tid & 31;
  if (lane == 0) { rs[warp] = s; rq[warp] = sq; }
  __syncthreads();
  float st = 0.f, sqt = 0.f;
#pragma unroll
  for (int i = 0; i < 8; i++) { st += rs[i]; sqt += rq[i]; }
  const float mu = st * (1.0f / DIM);
  const float var = sqt * (1.0f / DIM) - mu * mu;
  const float rstd = rsqrtf(var + 1e-5f);
  const float4 wv = reinterpret_cast<const float4*>(w)[tid];
  const float4 bv = reinterpret_cast<const float4*>(b)[tid];
  float4 o;
  o.x = (v.x - mu) * rstd * wv.x + bv.x;
  o.y = (v.y - mu) * rstd * wv.y + bv.y;
  o.z = (v.z - mu) * rstd * wv.z + bv.z;
  o.w = (v.w - mu) * rstd * wv.w + bv.w;
  reinterpret_cast<float4*>(out + (size_t)row * DIM)[tid] = o;
}

// ---------------- tf32 tensor-core GEMM NT (unchanged from R2) ----------------
#define ASTR 36

template <int EPI>
__global__ void __launch_bounds__(256) mma_nt(
    const float* __restrict__ A, const float* __restrict__ W,
    const float* __restrict__ bias, const float* __restrict__ res,
    float* __restrict__ C, int M, int N, int K) {
  extern __shared__ float sm[];
  float* const Asm = sm;
  float* const Bsm = sm + 2 * 128 * ASTR;

  const int bm = blockIdx.y * 128;
  const int bn = blockIdx.x * 128;
  const int tid = threadIdx.x;
  const int lane = tid & 31;
  const int warp = tid >> 5;
  const int wm = (warp >> 1) * 32;
  const int wn = (warp & 1) * 64;
  const int lg = lane >> 2;
  const int lt = lane & 3;

  float acc[2][8][4];
#pragma unroll
  for (int mt = 0; mt < 2; mt++)
#pragma unroll
    for (int nt = 0; nt < 8; nt++)
#pragma unroll
      for (int i = 0; i < 4; i++) acc[mt][nt][i] = 0.f;

  const int lr = tid >> 3;
  const int lc = (tid & 7) * 4;
  float4 ra[4], rb[4];
  const int NIT = K >> 5;

#pragma unroll
  for (int i = 0; i < 4; i++) {
    ra[i] = *reinterpret_cast<const float4*>(A + (size_t)(bm + lr + i * 32) * K + lc);
    rb[i] = *reinterpret_cast<const float4*>(W + (size_t)(bn + lr + i * 32) * K + lc);
  }
#pragma unroll
  for (int i = 0; i < 4; i++) {
    float* pa = Asm + (lr + i * 32) * ASTR + lc;
    pa[0] = to_tf32(ra[i].x); pa[1] = to_tf32(ra[i].y);
    pa[2] = to_tf32(ra[i].z); pa[3] = to_tf32(ra[i].w);
    float* pb = Bsm + (lr + i * 32) * ASTR + lc;
    pb[0] = to_tf32(rb[i].x); pb[1] = to_tf32(rb[i].y);
    pb[2] = to_tf32(rb[i].z); pb[3] = to_tf32(rb[i].w);
  }
  __syncthreads();

  for (int it = 0; it < NIT; it++) {
    const int buf = it & 1;
    if (it + 1 < NIT) {
      const int k0 = (it + 1) << 5;
#pragma unroll
      for (int i = 0; i < 4; i++) {
        ra[i] = *reinterpret_cast<const float4*>(A + (size_t)(bm + lr + i * 32) * K + k0 + lc);
        rb[i] = *reinterpret_cast<const float4*>(W + (size_t)(bn + lr + i * 32) * K + k0 + lc);
      }
    }

    const float* Ab = Asm + buf * 128 * ASTR;
    const float* Bb = Bsm + buf * 128 * ASTR;
#pragma unroll
    for (int kk = 0; kk < 4; kk++) {
      const int k = kk * 8;
      uint32_t af[2][4];
#pragma unroll
      for (int mt = 0; mt < 2; mt++) {
        const int rbase = wm + mt * 16;
        af[mt][0] = __float_as_uint(Ab[(rbase + lg) * ASTR + k + lt]);
        af[mt][1] = __float_as_uint(Ab[(rbase + 8 + lg) * ASTR + k + lt]);
        af[mt][2] = __float_as_uint(Ab[(rbase + lg) * ASTR + k + 4 + lt]);
        af[mt][3] = __float_as_uint(Ab[(rbase + 8 + lg) * ASTR + k + 4 + lt]);
      }
#pragma unroll
      for (int nt = 0; nt < 8; nt++) {
        const int nbase = wn + nt * 8;
        uint32_t b0 = __float_as_uint(Bb[(nbase + lg) * ASTR + k + lt]);
        uint32_t b1 = __float_as_uint(Bb[(nbase + lg) * ASTR + k + 4 + lt]);
#pragma unroll
        for (int mt = 0; mt < 2; mt++) {
          asm volatile(
              "mma.sync.aligned.m16n8k8.row.col.f32.tf32.tf32.f32 "
              "{%0,%1,%2,%3}, {%4,%5,%6,%7}, {%8,%9}, {%0,%1,%2,%3};"
              : "+f"(acc[mt][nt][0]), "+f"(acc[mt][nt][1]),
                "+f"(acc[mt][nt][2]), "+f"(acc[mt][nt][3])
              : "r"(af[mt][0]), "r"(af[mt][1]), "r"(af[mt][2]), "r"(af[mt][3]),
                "r"(b0), "r"(b1));
        }
      }
    }

    if (it + 1 < NIT) {
      const int nbuf = (it + 1) & 1;
      float* Aw = Asm + nbuf * 128 * ASTR;
      float* Bw = Bsm + nbuf * 128 * ASTR;
#pragma unroll
      for (int i = 0; i < 4; i++) {
        float* pa = Aw + (lr + i * 32) * ASTR + lc;
        pa[0] = to_tf32(ra[i].x); pa[1] = to_tf32(ra[i].y);
        pa[2] = to_tf32(ra[i].z); pa[3] = to_tf32(ra[i].w);
        float* pb = Bw + (lr + i * 32) * ASTR + lc;
        pb[0] = to_tf32(rb[i].x); pb[1] = to_tf32(rb[i].y);
        pb[2] = to_tf32(rb[i].z); pb[3] = to_tf32(rb[i].w);
      }
    }
    __syncthreads();
  }

#pragma unroll
  for (int mt = 0; mt < 2; mt++) {
#pragma unroll
    for (int nt = 0; nt < 8; nt++) {
      const int c0 = bn + wn + nt * 8 + 2 * lt;
      const float2 bb = *reinterpret_cast<const float2*>(bias + c0);
#pragma unroll
      for (int rh = 0; rh < 2; rh++) {
        const int row = bm + wm + mt * 16 + lg + rh * 8;
        float2 o;
        o.x = acc[mt][nt][rh * 2 + 0] + bb.x;
        o.y = acc[mt][nt][rh * 2 + 1] + bb.y;
        if (EPI == 1) {
          const float2 rr = *reinterpret_cast<const float2*>(res + (size_t)row * N + c0);
          o.x += rr.x; o.y += rr.y;
        } else if (EPI == 2) {
          o.x = 0.5f * o.x * (1.0f + erff(o.x * 0.70710678118654752f));
          o.y = 0.5f * o.y * (1.0f + erff(o.y * 0.70710678118654752f));
        }
        *reinterpret_cast<float2*>(C + (size_t)row * N + c0) = o;
      }
    }
  }
}

#define MMA_SMEM (4 * 128 * ASTR * 4)

// ---------------- tf32 tensor-core flash attention ----------------
// CTA: 256 threads = 8 warps; 128 q-rows per CTA (16 per warp); kv tiles of 64.
// Q prescaled by 1/8. S and PV both via mma.sync m16n8k8 tf32.
#define QSTR 68  // 64+4: A/B frag LDS conflict-free (stride % 32 == 4)
#define VSTR 72  // 64+8: V B-frag LDS conflict-free (stride % 32 == 8)
#define ATTN_SMEM ((128 * QSTR + 64 * QSTR + 64 * VSTR + 128 * QSTR) * 4)

__global__ void __launch_bounds__(256) attn_mma(
    const float* __restrict__ qkv, float* __restrict__ out) {
  extern __shared__ float sma[];
  float* const Qs = sma;                          // [128][QSTR]
  float* const Ks = Qs + 128 * QSTR;              // [64][QSTR]
  float* const Vs = Ks + 64 * QSTR;               // [64][VSTR]
  float* const Ps = Vs + 64 * VSTR;               // [128][QSTR]

  const int tid = threadIdx.x;
  const int lane = tid & 31;
  const int warp = tid >> 5;
  const int lg = lane >> 2;
  const int lt = lane & 3;
  const int bh = blockIdx.y;
  const int b = bh >> 4, h = bh & 15;
  const int q0 = blockIdx.x * 128;
  const size_t base = (size_t)b * 1024 * 3072 + (size_t)h * 64;

  // load Q tile [128 x 64], prescale by 0.125, tf32-round
  {
    const int row = tid >> 1;
    const int c = (tid & 1) * 32;
    const float* src = qkv + base + (size_t)(q0 + row) * 3072 + c;
    float* dst = Qs + row * QSTR + c;
#pragma unroll
    for (int i = 0; i < 8; i++) {
      const float4 v = *reinterpret_cast<const float4*>(src + i * 4);
      dst[i * 4 + 0] = to_tf32(v.x * 0.125f);
      dst[i * 4 + 1] = to_tf32(v.y * 0.125f);
      dst[i * 4 + 2] = to_tf32(v.z * 0.125f);
      dst[i * 4 + 3] = to_tf32(v.w * 0.125f);
    }
  }

  float m_prev0 = -INFINITY, m_prev1 = -INFINITY;
  float l0 = 0.f, l1 = 0.f;
  float oacc[8][4];
#pragma unroll
  for (int nt = 0; nt < 8; nt++)
#pragma unroll
    for (int i = 0; i < 4; i++) oacc[nt][i] = 0.f;

  float* const Pw = Ps + warp * 16 * QSTR;
  const float* const Qw = Qs + warp * 16 * QSTR;

  for (int t = 0; t < 16; t++) {
    __syncthreads();
    // load K,V tile [64 x 64] each
    {
      const int row = tid >> 2;
      const int c = (tid & 3) * 16;
      const float* ksrc = qkv + base + (size_t)(t * 64 + row) * 3072 + 1024 + c;
      const float* vsrc = ksrc + 1024;
      float* kd = Ks + row * QSTR + c;
      float* vd = Vs + row * VSTR + c;
#pragma unroll
      for (int i = 0; i < 4; i++) {
        const float4 kv = *reinterpret_cast<const float4*>(ksrc + i * 4);
        kd[i * 4 + 0] = to_tf32(kv.x); kd[i * 4 + 1] = to_tf32(kv.y);
        kd[i * 4 + 2] = to_tf32(kv.z); kd[i * 4 + 3] = to_tf32(kv.w);
        const float4 vv = *reinterpret_cast<const float4*>(vsrc + i * 4);
        vd[i * 4 + 0] = to_tf32(vv.x); vd[i * 4 + 1] = to_tf32(vv.y);
        vd[i * 4 + 2] = to_tf32(vv.z); vd[i * 4 + 3] = to_tf32(vv.w);
      }
    }
    __syncthreads();

    // S = Qs @ Ks^T  (warp: 16x64)
    float sacc[8][4];
#pragma unroll
    for (int nt = 0; nt < 8; nt++)
#pragma unroll
      for (int i = 0; i < 4; i++) sacc[nt][i] = 0.f;

#pragma unroll
    for (int kc = 0; kc < 8; kc++) {
      const int k = kc * 8;
      uint32_t a0 = __float_as_uint(Qw[(lg) * QSTR + k + lt]);
      uint32_t a1 = __float_as_uint(Qw[(lg + 8) * QSTR + k + lt]);
      uint32_t a2 = __float_as_uint(Qw[(lg) * QSTR + k + 4 + lt]);
      uint32_t a3 = __float_as_uint(Qw[(lg + 8) * QSTR + k + 4 + lt]);
#pragma unroll
      for (int nt = 0; nt < 8; nt++) {
        uint32_t b0 = __float_as_uint(Ks[(nt * 8 + lg) * QSTR + k + lt]);
        uint32_t b1 = __float_as_uint(Ks[(nt * 8 + lg) * QSTR + k + 4 + lt]);
        asm volatile(
            "mma.sync.aligned.m16n8k8.row.col.f32.tf32.tf32.f32 "
            "{%0,%1,%2,%3}, {%4,%5,%6,%7}, {%8,%9}, {%0,%1,%2,%3};"
            : "+f"(sacc[nt][0]), "+f"(sacc[nt][1]),
              "+f"(sacc[nt][2]), "+f"(sacc[nt][3])
            : "r"(a0), "r"(a1), "r"(a2), "r"(a3), "r"(b0), "r"(b1));
      }
    }

    // online softmax on C frags: rows lg (vals 0,1) and lg+8 (vals 2,3)
    float mx0 = -INFINITY, mx1 = -INFINITY;
#pragma unroll
    for (int nt = 0; nt < 8; nt++) {
      mx0 = fmaxf(mx0, fmaxf(sacc[nt][0], sacc[nt][1]));
      mx1 = fmaxf(mx1, fmaxf(sacc[nt][2], sacc[nt][3]));
    }
    mx0 = fmaxf(mx0, __shfl_xor_sync(0xffffffffu, mx0, 1));
    mx0 = fmaxf(mx0, __shfl_xor_sync(0xffffffffu, mx0, 2));
    mx1 = fmaxf(mx1, __shfl_xor_sync(0xffffffffu, mx1, 1));
    mx1 = fmaxf(mx1, __shfl_xor_sync(0xffffffffu, mx1, 2));
    const float mnew0 = fmaxf(m_prev0, mx0);
    const float mnew1 = fmaxf(m_prev1, mx1);
    const float f0 = expf(m_prev0 - mnew0);
    const float f1 = expf(m_prev1 - mnew1);
    float rsum0 = 0.f, rsum1 = 0.f;
#pragma unroll
    for (int nt = 0; nt < 8; nt++) {
      const float p0 = to_tf32(expf(sacc[nt][0] - mnew0));
      const float p1 = to_tf32(expf(sacc[nt][1] - mnew0));
      const float p2 = to_tf32(expf(sacc[nt][2] - mnew1));
      const float p3 = to_tf32(expf(sacc[nt][3] - mnew1));
      rsum0 += p0 + p1; rsum1 += p2 + p3;
      sacc[nt][0] = p0; sacc[nt][1] = p1; sacc[nt][2] = p2; sacc[nt][3] = p3;
    }
    rsum0 += __shfl_xor_sync(0xffffffffu, rsum0, 1);
    rsum0 += __shfl_xor_sync(0xffffffffu, rsum0, 2);
    rsum1 += __shfl_xor_sync(0xffffffffu, rsum1, 1);
    rsum1 += __shfl_xor_sync(0xffffffffu, rsum1, 2);
    l0 = l0 * f0 + rsum0;
    l1 = l1 * f1 + rsum1;
    m_prev0 = mnew0; m_prev1 = mnew1;
#pragma unroll
    for (int nt = 0; nt < 8; nt++) {
      oacc[nt][0] *= f0; oacc[nt][1] *= f0;
      oacc[nt][2] *= f1; oacc[nt][3] *= f1;
    }

    // stage P to smem (per-warp region), then read back as A fragments
#pragma unroll
    for (int nt = 0; nt < 8; nt++) {
      *reinterpret_cast<float2*>(Pw + lg * QSTR + nt * 8 + 2 * lt) =
          make_float2(sacc[nt][0], sacc[nt][1]);
      *reinterpret_cast<float2*>(Pw + (lg + 8) * QSTR + nt * 8 + 2 * lt) =
          make_float2(sacc[nt][2], sacc[nt][3]);
    }
    __syncwarp();

    // O += P @ V   (A = P[16 x 64], B = V[64 x 64])
#pragma unroll
    for (int cc = 0; cc < 8; cc++) {
      const int c = cc * 8;
      uint32_t a0 = __float_as_uint(Pw[(lg) * QSTR + c + lt]);
      uint32_t a1 = __float_as_uint(Pw[(lg + 8) * QSTR + c + lt]);
      uint32_t a2 = __float_as_uint(Pw[(lg) * QSTR + c + 4 + lt]);
      uint32_t a3 = __float_as_uint(Pw[(lg + 8) * QSTR + c + 4 + lt]);
#pragma unroll
      for (int nt = 0; nt < 8; nt++) {
        uint32_t b0 = __float_as_uint(Vs[(c + lt) * VSTR + nt * 8 + lg]);
        uint32_t b1 = __float_as_uint(Vs[(c + 4 + lt) * VSTR + nt * 8 + lg]);
        asm volatile(
            "mma.sync.aligned.m16n8k8.row.col.f32.tf32.tf32.f32 "
            "{%0,%1,%2,%3}, {%4,%5,%6,%7}, {%8,%9}, {%0,%1,%2,%3};"
            : "+f"(oacc[nt][0]), "+f"(oacc[nt][1]),
              "+f"(oacc[nt][2]), "+f"(oacc[nt][3])
            : "r"(a0), "r"(a1), "r"(a2), "r"(a3), "r"(b0), "r"(b1));
      }
    }
  }

  // epilogue: O /= l, write [row][h*64 + d]
  const float inv0 = 1.0f / l0;
  const float inv1 = 1.0f / l1;
  const int r0 = q0 + warp * 16 + lg;
  const int r1 = r0 + 8;
#pragma unroll
  for (int nt = 0; nt < 8; nt++) {
    const int d = h * 64 + nt * 8 + 2 * lt;
    *reinterpret_cast<float2*>(out + (size_t)(b * 1024 + r0) * 1024 + d) =
        make_float2(oacc[nt][0] * inv0, oacc[nt][1] * inv0);
    *reinterpret_cast<float2*>(out + (size_t)(b * 1024 + r1) * 1024 + d) =
        make_float2(oacc[nt][2] * inv1, oacc[nt][3] * inv1);
  }
}

// ---------------- launch ----------------
extern "C" void kernel_launch(void* const* d_in, const int* in_sizes, int n_in,
                              void* d_out, int out_size) {
  const float* x = (const float*)d_in[0];
  const float* ln1w = (const float*)d_in[1];
  const float* ln1b = (const float*)d_in[2];
  const float* qkvw = (const float*)d_in[3];
  const float* qkvb = (const float*)d_in[4];
  const float* outw = (const float*)d_in[5];
  const float* outb = (const float*)d_in[6];
  const float* ln2w = (const float*)d_in[7];
  const float* ln2b = (const float*)d_in[8];
  const float* fc1w = (const float*)d_in[9];
  const float* fc1b = (const float*)d_in[10];
  const float* fc2w = (const float*)d_in[11];
  const float* fc2b = (const float*)d_in[12];
  float* out = (float*)d_out;

  float *h, *qkv, *attno, *x1, *ff;
  cudaGetSymbolAddress((void**)&h, g_h);
  cudaGetSymbolAddress((void**)&qkv, g_qkv);
  cudaGetSymbolAddress((void**)&attno, g_attno);
  cudaGetSymbolAddress((void**)&x1, g_x1);
  cudaGetSymbolAddress((void**)&ff, g_ff);

  cudaFuncSetAttribute(attn_mma,
                       cudaFuncAttributeMaxDynamicSharedMemorySize, ATTN_SMEM);
  cudaFuncSetAttribute(mma_nt<0>,
                       cudaFuncAttributeMaxDynamicSharedMemorySize, MMA_SMEM);
  cudaFuncSetAttribute(mma_nt<1>,
                       cudaFuncAttributeMaxDynamicSharedMemorySize, MMA_SMEM);
  cudaFuncSetAttribute(mma_nt<2>,
                       cudaFuncAttributeMaxDynamicSharedMemorySize, MMA_SMEM);

  // LN1
  ln_kernel<<<NTOK, 256>>>(x, ln1w, ln1b, h);
  // QKV: [8192,1024] @ [3072,1024]^T
  mma_nt<0><<<dim3(3072 / 128, NTOK / 128), 256, MMA_SMEM>>>(
      h, qkvw, qkvb, nullptr, qkv, NTOK, 3072, 1024);
  // attention (tensor core)
  attn_mma<<<dim3(1024 / 128, 128), 256, ATTN_SMEM>>>(qkv, attno);
  // out projection + residual
  mma_nt<1><<<dim3(1024 / 128, NTOK / 128), 256, MMA_SMEM>>>(
      attno, outw, outb, x, x1, NTOK, 1024, 1024);
  // LN2
  ln_kernel<<<NTOK, 256>>>(x1, ln2w, ln2b, h);
  // FC1 + GELU
  mma_nt<2><<<dim3(4096 / 128, NTOK / 128), 256, MMA_SMEM>>>(
      h, fc1w, fc1b, nullptr, ff, NTOK, 4096, 1024);
  // FC2 + residual -> output
  mma_nt<1><<<dim3(1024 / 128, NTOK / 128), 256, MMA_SMEM>>>(
      ff, fc2w, fc2b, x1, out, NTOK, 1024, 4096);
}

// round 4
// speedup vs baseline: 3.5592x; 1.2192x over previous
#include <cuda_runtime.h>
#include <math.h>
#include <stdint.h>

#define NTOK 8192
#define DIM 1024

// ---------------- scratch (device globals; no allocation) ----------------
__device__ float g_h[NTOK * DIM];
__device__ float g_qkv[NTOK * 3 * DIM];
__device__ float g_attno[NTOK * DIM];
__device__ float g_x1[NTOK * DIM];
__device__ float g_ff[NTOK * 4096];
// tf32-rounded weight copies
__device__ float g_wq[3 * DIM * DIM];
__device__ float g_wo[DIM * DIM];
__device__ float g_w1[4096 * DIM];
__device__ float g_w2[DIM * 4096];

__device__ __forceinline__ float to_tf32(float x) {
  uint32_t u;
  asm("cvt.rna.tf32.f32 %0, %1;" : "=r"(u) : "f"(x));
  return __uint_as_float(u);
}

__device__ __forceinline__ void cp16(uint32_t dst, const void* src) {
  asm volatile("cp.async.cg.shared.global [%0], [%1], 16;" ::"r"(dst), "l"(src));
}

// ---------------- weight rounding pass ----------------
__global__ void __launch_bounds__(256) round_copy(
    const float* __restrict__ in, float* __restrict__ out, int n4) {
  const int i = blockIdx.x * 256 + threadIdx.x;
  if (i < n4) {
    const float4 v = reinterpret_cast<const float4*>(in)[i];
    float4 o;
    o.x = to_tf32(v.x); o.y = to_tf32(v.y);
    o.z = to_tf32(v.z); o.w = to_tf32(v.w);
    reinterpret_cast<float4*>(out)[i] = o;
  }
}

// ---------------- LayerNorm (tf32-rounded output: feeds GEMM A) -----------
__global__ void __launch_bounds__(256) ln_kernel(
    const float* __restrict__ in, const float* __restrict__ w,
    const float* __restrict__ b, float* __restrict__ out) {
  const int row = blockIdx.x;
  const int tid = threadIdx.x;
  const float4 v = reinterpret_cast<const float4*>(in + (size_t)row * DIM)[tid];
  float s = v.x + v.y + v.z + v.w;
  float sq = v.x * v.x + v.y * v.y + v.z * v.z + v.w * v.w;
#pragma unroll
  for (int o = 16; o > 0; o >>= 1) {
    s += __shfl_xor_sync(0xffffffffu, s, o);
    sq += __shfl_xor_sync(0xffffffffu, sq, o);
  }
  __shared__ float rs[8], rq[8];
  const int warp = tid >> 5, lane = tid & 31;
  if (lane == 0) { rs[warp] = s; rq[warp] = sq; }
  __syncthreads();
  float st = 0.f, sqt = 0.f;
#pragma unroll
  for (int i = 0; i < 8; i++) { st += rs[i]; sqt += rq[i]; }
  const float mu = st * (1.0f / DIM);
  const float var = sqt * (1.0f / DIM) - mu * mu;
  const float rstd = rsqrtf(var + 1e-5f);
  const float4 wv = reinterpret_cast<const float4*>(w)[tid];
  const float4 bv = reinterpret_cast<const float4*>(b)[tid];
  float4 o;
  o.x = to_tf32((v.x - mu) * rstd * wv.x + bv.x);
  o.y = to_tf32((v.y - mu) * rstd * wv.y + bv.y);
  o.z = to_tf32((v.z - mu) * rstd * wv.z + bv.z);
  o.w = to_tf32((v.w - mu) * rstd * wv.w + bv.w);
  reinterpret_cast<float4*>(out + (size_t)row * DIM)[tid] = o;
}

// ---------------- tf32 tensor-core GEMM NT with cp.async pipeline ----------
// C[M,N] = A[M,K] @ W[N,K]^T + bias (+epilogue). Inputs pre-rounded to tf32.
// EPI: 0 = bias, 1 = bias + residual, 2 = bias + exact GELU (tf32-rounded out)
#define ASTR 36
#define STAGE (256 * ASTR)  // floats per stage (A 128xASTR + B 128xASTR)
#define MMA_SMEM (2 * STAGE * 4)

template <int EPI>
__global__ void __launch_bounds__(256, 2) mma_nt(
    const float* __restrict__ A, const float* __restrict__ W,
    const float* __restrict__ bias, const float* __restrict__ res,
    float* __restrict__ C, int M, int N, int K) {
  extern __shared__ float sm[];
  const uint32_t smb = (uint32_t)__cvta_generic_to_shared(sm);

  const int bm = blockIdx.y * 128;
  const int bn = blockIdx.x * 128;
  const int tid = threadIdx.x;
  const int lane = tid & 31;
  const int warp = tid >> 5;
  const int wm = (warp >> 1) * 32;
  const int wn = (warp & 1) * 64;
  const int lg = lane >> 2;
  const int lt = lane & 3;

  float acc[2][8][4];
#pragma unroll
  for (int mt = 0; mt < 2; mt++)
#pragma unroll
    for (int nt = 0; nt < 8; nt++)
#pragma unroll
      for (int i = 0; i < 4; i++) acc[mt][nt][i] = 0.f;

  const int lr = tid >> 3;        // base row 0..31 (+32*i)
  const int lc4 = (tid & 7) * 4;  // col 0,4,...,28
  const int NIT = K >> 5;

  // stage loader: A rows bm.., W rows bn.., k-cols [k0, k0+32)
  auto load_stage = [&](int s, int k0) {
    const uint32_t abase = smb + (uint32_t)(s * STAGE) * 4u;
    const uint32_t bbase = abase + (uint32_t)(128 * ASTR) * 4u;
#pragma unroll
    for (int i = 0; i < 4; i++) {
      const int row = lr + i * 32;
      cp16(abase + (uint32_t)(row * ASTR + lc4) * 4u,
           A + (size_t)(bm + row) * K + k0 + lc4);
      cp16(bbase + (uint32_t)(row * ASTR + lc4) * 4u,
           W + (size_t)(bn + row) * K + k0 + lc4);
    }
    asm volatile("cp.async.commit_group;");
  };

  load_stage(0, 0);

  for (int it = 0; it < NIT; it++) {
    if (it + 1 < NIT) {
      load_stage((it + 1) & 1, (it + 1) << 5);
      asm volatile("cp.async.wait_group 1;");
    } else {
      asm volatile("cp.async.wait_group 0;");
    }
    __syncthreads();

    const float* Ab = sm + (it & 1) * STAGE;
    const float* Bb = Ab + 128 * ASTR;
#pragma unroll
    for (int kk = 0; kk < 4; kk++) {
      const int k = kk * 8;
      uint32_t af[2][4];
#pragma unroll
      for (int mt = 0; mt < 2; mt++) {
        const int rbase = wm + mt * 16;
        af[mt][0] = __float_as_uint(Ab[(rbase + lg) * ASTR + k + lt]);
        af[mt][1] = __float_as_uint(Ab[(rbase + 8 + lg) * ASTR + k + lt]);
        af[mt][2] = __float_as_uint(Ab[(rbase + lg) * ASTR + k + 4 + lt]);
        af[mt][3] = __float_as_uint(Ab[(rbase + 8 + lg) * ASTR + k + 4 + lt]);
      }
#pragma unroll
      for (int nt = 0; nt < 8; nt++) {
        const int nbase = wn + nt * 8;
        uint32_t b0 = __float_as_uint(Bb[(nbase + lg) * ASTR + k + lt]);
        uint32_t b1 = __float_as_uint(Bb[(nbase + lg) * ASTR + k + 4 + lt]);
#pragma unroll
        for (int mt = 0; mt < 2; mt++) {
          asm volatile(
              "mma.sync.aligned.m16n8k8.row.col.f32.tf32.tf32.f32 "
              "{%0,%1,%2,%3}, {%4,%5,%6,%7}, {%8,%9}, {%0,%1,%2,%3};"
              : "+f"(acc[mt][nt][0]), "+f"(acc[mt][nt][1]),
                "+f"(acc[mt][nt][2]), "+f"(acc[mt][nt][3])
              : "r"(af[mt][0]), "r"(af[mt][1]), "r"(af[mt][2]), "r"(af[mt][3]),
                "r"(b0), "r"(b1));
        }
      }
    }
    __syncthreads();
  }

  // epilogue
#pragma unroll
  for (int mt = 0; mt < 2; mt++) {
#pragma unroll
    for (int nt = 0; nt < 8; nt++) {
      const int c0 = bn + wn + nt * 8 + 2 * lt;
      const float2 bb = *reinterpret_cast<const float2*>(bias + c0);
#pragma unroll
      for (int rh = 0; rh < 2; rh++) {
        const int row = bm + wm + mt * 16 + lg + rh * 8;
        float2 o;
        o.x = acc[mt][nt][rh * 2 + 0] + bb.x;
        o.y = acc[mt][nt][rh * 2 + 1] + bb.y;
        if (EPI == 1) {
          const float2 rr = *reinterpret_cast<const float2*>(res + (size_t)row * N + c0);
          o.x += rr.x; o.y += rr.y;
        } else if (EPI == 2) {
          o.x = to_tf32(0.5f * o.x * (1.0f + erff(o.x * 0.70710678118654752f)));
          o.y = to_tf32(0.5f * o.y * (1.0f + erff(o.y * 0.70710678118654752f)));
        }
        *reinterpret_cast<float2*>(C + (size_t)row * N + c0) = o;
      }
    }
  }
}

// ---------------- tf32 tensor-core flash attention (tf32-rounded output) ---
#define QSTR 68
#define VSTR 72
#define ATTN_SMEM ((128 * QSTR + 64 * QSTR + 64 * VSTR + 128 * QSTR) * 4)

__global__ void __launch_bounds__(256) attn_mma(
    const float* __restrict__ qkv, float* __restrict__ out) {
  extern __shared__ float sma[];
  float* const Qs = sma;
  float* const Ks = Qs + 128 * QSTR;
  float* const Vs = Ks + 64 * QSTR;
  float* const Ps = Vs + 64 * VSTR;

  const int tid = threadIdx.x;
  const int lane = tid & 31;
  const int warp = tid >> 5;
  const int lg = lane >> 2;
  const int lt = lane & 3;
  const int bh = blockIdx.y;
  const int b = bh >> 4, h = bh & 15;
  const int q0 = blockIdx.x * 128;
  const size_t base = (size_t)b * 1024 * 3072 + (size_t)h * 64;

  {
    const int row = tid >> 1;
    const int c = (tid & 1) * 32;
    const float* src = qkv + base + (size_t)(q0 + row) * 3072 + c;
    float* dst = Qs + row * QSTR + c;
#pragma unroll
    for (int i = 0; i < 8; i++) {
      const float4 v = *reinterpret_cast<const float4*>(src + i * 4);
      dst[i * 4 + 0] = to_tf32(v.x * 0.125f);
      dst[i * 4 + 1] = to_tf32(v.y * 0.125f);
      dst[i * 4 + 2] = to_tf32(v.z * 0.125f);
      dst[i * 4 + 3] = to_tf32(v.w * 0.125f);
    }
  }

  float m_prev0 = -INFINITY, m_prev1 = -INFINITY;
  float l0 = 0.f, l1 = 0.f;
  float oacc[8][4];
#pragma unroll
  for (int nt = 0; nt < 8; nt++)
#pragma unroll
    for (int i = 0; i < 4; i++) oacc[nt][i] = 0.f;

  float* const Pw = Ps + warp * 16 * QSTR;
  const float* const Qw = Qs + warp * 16 * QSTR;

  for (int t = 0; t < 16; t++) {
    __syncthreads();
    {
      const int row = tid >> 2;
      const int c = (tid & 3) * 16;
      const float* ksrc = qkv + base + (size_t)(t * 64 + row) * 3072 + 1024 + c;
      const float* vsrc = ksrc + 1024;
      float* kd = Ks + row * QSTR + c;
      float* vd = Vs + row * VSTR + c;
#pragma unroll
      for (int i = 0; i < 4; i++) {
        const float4 kv = *reinterpret_cast<const float4*>(ksrc + i * 4);
        kd[i * 4 + 0] = to_tf32(kv.x); kd[i * 4 + 1] = to_tf32(kv.y);
        kd[i * 4 + 2] = to_tf32(kv.z); kd[i * 4 + 3] = to_tf32(kv.w);
        const float4 vv = *reinterpret_cast<const float4*>(vsrc + i * 4);
        vd[i * 4 + 0] = to_tf32(vv.x); vd[i * 4 + 1] = to_tf32(vv.y);
        vd[i * 4 + 2] = to_tf32(vv.z); vd[i * 4 + 3] = to_tf32(vv.w);
      }
    }
    __syncthreads();

    float sacc[8][4];
#pragma unroll
    for (int nt = 0; nt < 8; nt++)
#pragma unroll
      for (int i = 0; i < 4; i++) sacc[nt][i] = 0.f;

#pragma unroll
    for (int kc = 0; kc < 8; kc++) {
      const int k = kc * 8;
      uint32_t a0 = __float_as_uint(Qw[(lg) * QSTR + k + lt]);
      uint32_t a1 = __float_as_uint(Qw[(lg + 8) * QSTR + k + lt]);
      uint32_t a2 = __float_as_uint(Qw[(lg) * QSTR + k + 4 + lt]);
      uint32_t a3 = __float_as_uint(Qw[(lg + 8) * QSTR + k + 4 + lt]);
#pragma unroll
      for (int nt = 0; nt < 8; nt++) {
        uint32_t b0 = __float_as_uint(Ks[(nt * 8 + lg) * QSTR + k + lt]);
        uint32_t b1 = __float_as_uint(Ks[(nt * 8 + lg) * QSTR + k + 4 + lt]);
        asm volatile(
            "mma.sync.aligned.m16n8k8.row.col.f32.tf32.tf32.f32 "
            "{%0,%1,%2,%3}, {%4,%5,%6,%7}, {%8,%9}, {%0,%1,%2,%3};"
            : "+f"(sacc[nt][0]), "+f"(sacc[nt][1]),
              "+f"(sacc[nt][2]), "+f"(sacc[nt][3])
            : "r"(a0), "r"(a1), "r"(a2), "r"(a3), "r"(b0), "r"(b1));
      }
    }

    float mx0 = -INFINITY, mx1 = -INFINITY;
#pragma unroll
    for (int nt = 0; nt < 8; nt++) {
      mx0 = fmaxf(mx0, fmaxf(sacc[nt][0], sacc[nt][1]));
      mx1 = fmaxf(mx1, fmaxf(sacc[nt][2], sacc[nt][3]));
    }
    mx0 = fmaxf(mx0, __shfl_xor_sync(0xffffffffu, mx0, 1));
    mx0 = fmaxf(mx0, __shfl_xor_sync(0xffffffffu, mx0, 2));
    mx1 = fmaxf(mx1, __shfl_xor_sync(0xffffffffu, mx1, 1));
    mx1 = fmaxf(mx1, __shfl_xor_sync(0xffffffffu, mx1, 2));
    const float mnew0 = fmaxf(m_prev0, mx0);
    const float mnew1 = fmaxf(m_prev1, mx1);
    const float f0 = expf(m_prev0 - mnew0);
    const float f1 = expf(m_prev1 - mnew1);
    float rsum0 = 0.f, rsum1 = 0.f;
#pragma unroll
    for (int nt = 0; nt < 8; nt++) {
      const float p0 = to_tf32(expf(sacc[nt][0] - mnew0));
      const float p1 = to_tf32(expf(sacc[nt][1] - mnew0));
      const float p2 = to_tf32(expf(sacc[nt][2] - mnew1));
      const float p3 = to_tf32(expf(sacc[nt][3] - mnew1));
      rsum0 += p0 + p1; rsum1 += p2 + p3;
      sacc[nt][0] = p0; sacc[nt][1] = p1; sacc[nt][2] = p2; sacc[nt][3] = p3;
    }
    rsum0 += __shfl_xor_sync(0xffffffffu, rsum0, 1);
    rsum0 += __shfl_xor_sync(0xffffffffu, rsum0, 2);
    rsum1 += __shfl_xor_sync(0xffffffffu, rsum1, 1);
    rsum1 += __shfl_xor_sync(0xffffffffu, rsum1, 2);
    l0 = l0 * f0 + rsum0;
    l1 = l1 * f1 + rsum1;
    m_prev0 = mnew0; m_prev1 = mnew1;
#pragma unroll
    for (int nt = 0; nt < 8; nt++) {
      oacc[nt][0] *= f0; oacc[nt][1] *= f0;
      oacc[nt][2] *= f1; oacc[nt][3] *= f1;
    }

#pragma unroll
    for (int nt = 0; nt < 8; nt++) {
      *reinterpret_cast<float2*>(Pw + lg * QSTR + nt * 8 + 2 * lt) =
          make_float2(sacc[nt][0], sacc[nt][1]);
      *reinterpret_cast<float2*>(Pw + (lg + 8) * QSTR + nt * 8 + 2 * lt) =
          make_float2(sacc[nt][2], sacc[nt][3]);
    }
    __syncwarp();

#pragma unroll
    for (int cc = 0; cc < 8; cc++) {
      const int c = cc * 8;
      uint32_t a0 = __float_as_uint(Pw[(lg) * QSTR + c + lt]);
      uint32_t a1 = __float_as_uint(Pw[(lg + 8) * QSTR + c + lt]);
      uint32_t a2 = __float_as_uint(Pw[(lg) * QSTR + c + 4 + lt]);
      uint32_t a3 = __float_as_uint(Pw[(lg + 8) * QSTR + c + 4 + lt]);
#pragma unroll
      for (int nt = 0; nt < 8; nt++) {
        uint32_t b0 = __float_as_uint(Vs[(c + lt) * VSTR + nt * 8 + lg]);
        uint32_t b1 = __float_as_uint(Vs[(c + 4 + lt) * VSTR + nt * 8 + lg]);
        asm volatile(
            "mma.sync.aligned.m16n8k8.row.col.f32.tf32.tf32.f32 "
            "{%0,%1,%2,%3}, {%4,%5,%6,%7}, {%8,%9}, {%0,%1,%2,%3};"
            : "+f"(oacc[nt][0]), "+f"(oacc[nt][1]),
              "+f"(oacc[nt][2]), "+f"(oacc[nt][3])
            : "r"(a0), "r"(a1), "r"(a2), "r"(a3), "r"(b0), "r"(b1));
      }
    }
  }

  const float inv0 = 1.0f / l0;
  const float inv1 = 1.0f / l1;
  const int r0 = q0 + warp * 16 + lg;
  const int r1 = r0 + 8;
#pragma unroll
  for (int nt = 0; nt < 8; nt++) {
    const int d = h * 64 + nt * 8 + 2 * lt;
    *reinterpret_cast<float2*>(out + (size_t)(b * 1024 + r0) * 1024 + d) =
        make_float2(to_tf32(oacc[nt][0] * inv0), to_tf32(oacc[nt][1] * inv0));
    *reinterpret_cast<float2*>(out + (size_t)(b * 1024 + r1) * 1024 + d) =
        make_float2(to_tf32(oacc[nt][2] * inv1), to_tf32(oacc[nt][3] * inv1));
  }
}

// ---------------- launch ----------------
extern "C" void kernel_launch(void* const* d_in, const int* in_sizes, int n_in,
                              void* d_out, int out_size) {
  const float* x = (const float*)d_in[0];
  const float* ln1w = (const float*)d_in[1];
  const float* ln1b = (const float*)d_in[2];
  const float* qkvw = (const float*)d_in[3];
  const float* qkvb = (const float*)d_in[4];
  const float* outw = (const float*)d_in[5];
  const float* outb = (const float*)d_in[6];
  const float* ln2w = (const float*)d_in[7];
  const float* ln2b = (const float*)d_in[8];
  const float* fc1w = (const float*)d_in[9];
  const float* fc1b = (const float*)d_in[10];
  const float* fc2w = (const float*)d_in[11];
  const float* fc2b = (const float*)d_in[12];
  float* out = (float*)d_out;

  float *h, *qkv, *attno, *x1, *ff, *wq, *wo, *w1, *w2;
  cudaGetSymbolAddress((void**)&h, g_h);
  cudaGetSymbolAddress((void**)&qkv, g_qkv);
  cudaGetSymbolAddress((void**)&attno, g_attno);
  cudaGetSymbolAddress((void**)&x1, g_x1);
  cudaGetSymbolAddress((void**)&ff, g_ff);
  cudaGetSymbolAddress((void**)&wq, g_wq);
  cudaGetSymbolAddress((void**)&wo, g_wo);
  cudaGetSymbolAddress((void**)&w1, g_w1);
  cudaGetSymbolAddress((void**)&w2, g_w2);

  cudaFuncSetAttribute(attn_mma,
                       cudaFuncAttributeMaxDynamicSharedMemorySize, ATTN_SMEM);
  cudaFuncSetAttribute(mma_nt<0>,
                       cudaFuncAttributeMaxDynamicSharedMemorySize, MMA_SMEM);
  cudaFuncSetAttribute(mma_nt<1>,
                       cudaFuncAttributeMaxDynamicSharedMemorySize, MMA_SMEM);
  cudaFuncSetAttribute(mma_nt<2>,
                       cudaFuncAttributeMaxDynamicSharedMemorySize, MMA_SMEM);

  // weight rounding (tf32-canonical copies)
  round_copy<<<(3 * DIM * DIM / 4 + 255) / 256, 256>>>(qkvw, wq, 3 * DIM * DIM / 4);
  round_copy<<<(DIM * DIM / 4 + 255) / 256, 256>>>(outw, wo, DIM * DIM / 4);
  round_copy<<<(4096 * DIM / 4 + 255) / 256, 256>>>(fc1w, w1, 4096 * DIM / 4);
  round_copy<<<(DIM * 4096 / 4 + 255) / 256, 256>>>(fc2w, w2, DIM * 4096 / 4);

  // LN1
  ln_kernel<<<NTOK, 256>>>(x, ln1w, ln1b, h);
  // QKV: [8192,1024] @ [3072,1024]^T
  mma_nt<0><<<dim3(3072 / 128, NTOK / 128), 256, MMA_SMEM>>>(
      h, wq, qkvb, nullptr, qkv, NTOK, 3072, 1024);
  // attention (tensor core)
  attn_mma<<<dim3(1024 / 128, 128), 256, ATTN_SMEM>>>(qkv, attno);
  // out projection + residual
  mma_nt<1><<<dim3(1024 / 128, NTOK / 128), 256, MMA_SMEM>>>(
      attno, wo, outb, x, x1, NTOK, 1024, 1024);
  // LN2
  ln_kernel<<<NTOK, 256>>>(x1, ln2w, ln2b, h);
  // FC1 + GELU
  mma_nt<2><<<dim3(4096 / 128, NTOK / 128), 256, MMA_SMEM>>>(
      h, w1, fc1b, nullptr, ff, NTOK, 4096, 1024);
  // FC2 + residual -> output
  mma_nt<1><<<dim3(1024 / 128, NTOK / 128), 256, MMA_SMEM>>>(
      ff, w2, fc2b, x1, out, NTOK, 1024, 4096);
}